// round 3
// baseline (speedup 1.0000x reference)
#include <cuda_runtime.h>
#include <math.h>

#define BATCH 32
#define NPTS 4096
#define IDIM 125
#define ADIM 128
#define KDIM 64
#define DMODEL 1024
#define HID 64
#define KSEL 256
#define EPSV 1e-6f
#define TILES_PER_BLOCK 8

// ---------------- scratch (device globals; no allocation allowed) ----------------
__device__ float g_sal[BATCH * NPTS];
__device__ float g_csal[BATCH * NPTS];
__device__ int   g_topidx[BATCH * KSEL];
__device__ float g_cloud[BATCH * KSEL * KDIM];

// ---------------- kernel 1: fused saliency MLP ----------------
// grid: BATCH * NPTS/(32*TILES_PER_BLOCK) blocks, 256 threads.
// W1 stays resident in smem across 8 tiles of 32 points.
// thread micro-tile: 2 points x 4 hidden. Fused relu + W2 dot + sigmoid.
__global__ __launch_bounds__(256) void saliency_kernel(
    const float* __restrict__ x, const float* __restrict__ W1,
    const float* __restrict__ b1, const float* __restrict__ W2,
    const float* __restrict__ b2)
{
    __shared__ float sx[32 * 126];    // x tile, padded stride (15.75KB)
    __shared__ float W1s[IDIM * HID]; // 125*64 = 8000 floats (31.25KB)

    const int groupsPerBatch = NPTS / (32 * TILES_PER_BLOCK); // 16
    const int b  = blockIdx.x / groupsPerBatch;
    const int g0 = (blockIdx.x % groupsPerBatch) * TILES_PER_BLOCK;
    const int tid = threadIdx.x;

    // load W1 (8000 floats) coalesced, once per block
    for (int i = tid; i < IDIM * HID; i += 256) W1s[i] = W1[i];

    const int pr = tid >> 4;      // 0..15 -> 2 points each
    const int hr = tid & 15;      // 0..15 -> 4 hidden each
    const int h0 = hr * 4;

    float4 b1v = *(const float4*)(b1 + h0);
    float4 w2v = *(const float4*)(W2 + h0);
    const float bias = b2[0];

    for (int t = 0; t < TILES_PER_BLOCK; t++) {
        const int p0 = (g0 + t) * 32;
        // load x tile: 32*125 = 4000 consecutive floats
        const float* xbase = x + ((long)b * NPTS + p0) * IDIM;
        __syncthreads();   // protect sx from previous iteration's readers
        for (int i = tid; i < 32 * IDIM; i += 256) {
            int p = i / IDIM, d = i - p * IDIM;
            sx[p * 126 + d] = xbase[i];
        }
        __syncthreads();

        float a00 = b1v.x, a01 = b1v.y, a02 = b1v.z, a03 = b1v.w;
        float a10 = b1v.x, a11 = b1v.y, a12 = b1v.z, a13 = b1v.w;

        const float* sxa = sx + (pr * 2 + 0) * 126;
        const float* sxb = sx + (pr * 2 + 1) * 126;
#pragma unroll 5
        for (int d = 0; d < IDIM; d++) {
            float xa = sxa[d];
            float xb = sxb[d];
            float4 w = *(const float4*)(W1s + d * HID + h0);
            a00 = fmaf(xa, w.x, a00); a01 = fmaf(xa, w.y, a01);
            a02 = fmaf(xa, w.z, a02); a03 = fmaf(xa, w.w, a03);
            a10 = fmaf(xb, w.x, a10); a11 = fmaf(xb, w.y, a11);
            a12 = fmaf(xb, w.z, a12); a13 = fmaf(xb, w.w, a13);
        }
        // relu + dot with W2
        float p0s = fmaxf(a00, 0.f) * w2v.x + fmaxf(a01, 0.f) * w2v.y
                  + fmaxf(a02, 0.f) * w2v.z + fmaxf(a03, 0.f) * w2v.w;
        float p1s = fmaxf(a10, 0.f) * w2v.x + fmaxf(a11, 0.f) * w2v.y
                  + fmaxf(a12, 0.f) * w2v.z + fmaxf(a13, 0.f) * w2v.w;
        // reduce across the 16 hr lanes (same pr group = 16 consecutive lanes)
#pragma unroll
        for (int off = 8; off > 0; off >>= 1) {
            p0s += __shfl_down_sync(0xFFFFFFFFu, p0s, off, 16);
            p1s += __shfl_down_sync(0xFFFFFFFFu, p1s, off, 16);
        }
        if (hr == 0) {
            int pg0 = p0 + pr * 2;
            float s0 = 1.f / (1.f + expf(-(p0s + bias)));
            float s1 = 1.f / (1.f + expf(-(p1s + bias)));
            g_sal[b * NPTS + pg0]     = s0;
            g_sal[b * NPTS + pg0 + 1] = s1;
        }
    }
}

// ---------------- kernel 2: per-batch softmax + cumsum ----------------
// one block (1024 threads) per batch; 4 elements per thread.
__global__ __launch_bounds__(1024) void scan_kernel(float* __restrict__ ystar)
{
    __shared__ float wsum[32];
    __shared__ float woff[32];
    __shared__ float wesum[32];
    __shared__ float total_sh;

    const int b = blockIdx.x;
    const int tid = threadIdx.x;
    const int lane = tid & 31, wid = tid >> 5;

    float4 s4 = *(const float4*)(g_sal + b * NPTS + tid * 4);
    float s0 = s4.x;
    float s1 = s0 + s4.y;
    float s2 = s1 + s4.z;
    float s3 = s2 + s4.w;

    float e0 = expf(2.f * s4.x), e1 = expf(2.f * s4.y);
    float e2 = expf(2.f * s4.z), e3 = expf(2.f * s4.w);
    float esum = e0 + e1 + e2 + e3;

    // warp inclusive scan of per-thread totals
    float t = s3, incl = t;
#pragma unroll
    for (int off = 1; off < 32; off <<= 1) {
        float v = __shfl_up_sync(0xFFFFFFFFu, incl, off);
        if (lane >= off) incl += v;
    }
    // warp reduce esum
    float er = esum;
#pragma unroll
    for (int off = 16; off > 0; off >>= 1) er += __shfl_down_sync(0xFFFFFFFFu, er, off);
    if (lane == 31) wsum[wid] = incl;
    if (lane == 0)  wesum[wid] = er;
    __syncthreads();
    if (wid == 0) {
        float v = wsum[lane];
        float inc = v;
#pragma unroll
        for (int off = 1; off < 32; off <<= 1) {
            float u = __shfl_up_sync(0xFFFFFFFFu, inc, off);
            if (lane >= off) inc += u;
        }
        woff[lane] = inc - v; // exclusive
        float es = wesum[lane];
#pragma unroll
        for (int off = 16; off > 0; off >>= 1) es += __shfl_down_sync(0xFFFFFFFFu, es, off);
        if (lane == 0) total_sh = es;
    }
    __syncthreads();

    float base = woff[wid] + (incl - t); // exclusive prefix before this thread
    const float invn = 1.f / (float)NPTS;
    float4 c4;
    c4.x = (base + s0) * invn;
    c4.y = (base + s1) * invn;
    c4.z = (base + s2) * invn;
    c4.w = (base + s3) * invn;
    *(float4*)(g_csal + b * NPTS + tid * 4) = c4;

    float invtot = 1.f / total_sh;
    float4 y4;
    y4.x = e0 * invtot; y4.y = e1 * invtot; y4.z = e2 * invtot; y4.w = e3 * invtot;
    *(float4*)(ystar + b * NPTS + tid * 4) = y4;
}

// ---------------- kernel 3: per-batch top-256 via bitonic sort ----------------
// key = (~monotone(value) << 32) | index ; ascending sort => descending value,
// ascending index on ties (matches jax.lax.top_k).
__global__ __launch_bounds__(1024) void topk_kernel(const float* __restrict__ ystar)
{
    __shared__ unsigned long long keys[NPTS];
    const int b = blockIdx.x;
    const int tid = threadIdx.x;

    for (int i = tid; i < NPTS; i += 1024) {
        unsigned u = __float_as_uint(ystar[b * NPTS + i]);
        unsigned m = (u & 0x80000000u) ? ~u : (u | 0x80000000u);
        unsigned inv = ~m;
        keys[i] = ((unsigned long long)inv << 32) | (unsigned)i;
    }
    __syncthreads();

    for (int k = 2; k <= NPTS; k <<= 1) {
        for (int j = k >> 1; j > 0; j >>= 1) {
#pragma unroll 4
            for (int i = tid; i < NPTS; i += 1024) {
                int ixj = i ^ j;
                if (ixj > i) {
                    bool up = ((i & k) == 0);
                    unsigned long long a = keys[i];
                    unsigned long long c = keys[ixj];
                    if ((a > c) == up) { keys[i] = c; keys[ixj] = a; }
                }
            }
            __syncthreads();
        }
    }
    for (int t2 = tid; t2 < KSEL; t2 += 1024)
        g_topidx[b * KSEL + t2] = (int)(keys[t2] & 0xFFFFFFFFu);
}

// ---------------- kernel 4: dense anchor + normalize + lift (selected points only) --
// warp per selected point; 8 warps per block.
__global__ __launch_bounds__(256) void lift_kernel(
    const float* __restrict__ x, const float* __restrict__ lift_W,
    const float* __restrict__ lift_b, const float* __restrict__ mu,
    const float* __restrict__ sigma)
{
    __shared__ float Ws[ADIM * KDIM]; // 128*64 = 8192 floats = 32KB
    __shared__ float a_s[8][ADIM];

    const int tid = threadIdx.x;
    for (int i = tid; i < ADIM * KDIM; i += 256) Ws[i] = lift_W[i];
    __syncthreads();

    const int w = tid >> 5, lane = tid & 31;
    const int gk = blockIdx.x * 8 + w;   // global selected point 0..8191
    const int b = gk / KSEL;
    const int idx = g_topidx[gk];

    // each lane owns 4 anchor dims
    float v[4];
    const float* xr = x + ((long)b * NPTS + idx) * IDIM;
    float sal = g_sal[b * NPTS + idx];
    float cs  = g_csal[b * NPTS + idx];
    float pos = (float)idx * (1.f / (float)(NPTS - 1));
#pragma unroll
    for (int q = 0; q < 4; q++) {
        int d = lane * 4 + q;
        float val;
        if (d < IDIM)       val = xr[d];
        else if (d == 125)  val = sal;
        else if (d == 126)  val = pos;
        else                val = cs;
        v[q] = val;
    }
    float ss = v[0]*v[0] + v[1]*v[1] + v[2]*v[2] + v[3]*v[3];
#pragma unroll
    for (int off = 16; off > 0; off >>= 1) ss += __shfl_xor_sync(0xFFFFFFFFu, ss, off);
    float inv_nrm = 1.f / (sqrtf(ss) + EPSV);
#pragma unroll
    for (int q = 0; q < 4; q++) {
        int d = lane * 4 + q;
        a_s[w][d] = (v[q] * inv_nrm - mu[d]) / sigma[d];
    }
    __syncwarp();

    const int j = lane;
    float acc0 = lift_b[j], acc1 = lift_b[j + 32];
#pragma unroll 8
    for (int d = 0; d < ADIM; d++) {
        float f = a_s[w][d];
        acc0 = fmaf(f, Ws[d * KDIM + j], acc0);
        acc1 = fmaf(f, Ws[d * KDIM + j + 32], acc1);
    }
    g_cloud[gk * KDIM + j]      = acc0;
    g_cloud[gk * KDIM + j + 32] = acc1;
}

// ---------------- kernel 5: projection GEMM [8192,64]@[64,1024]+b ----------------
// block: 16 points x 1024 cols; thread: 16 points x 4 cols (float4).
__global__ __launch_bounds__(256) void proj_kernel(
    const float* __restrict__ proj_W, const float* __restrict__ proj_b,
    float* __restrict__ tokens)
{
    __shared__ float cs[16 * KDIM]; // 4KB
    const int tid = threadIdx.x;
    const int p0 = blockIdx.x * 16;

    for (int i = tid; i < 16 * KDIM; i += 256) cs[i] = g_cloud[p0 * KDIM + i];
    __syncthreads();

    const int d4 = tid * 4; // column group
    float4 acc[16];
#pragma unroll
    for (int p = 0; p < 16; p++) acc[p] = make_float4(0.f, 0.f, 0.f, 0.f);

#pragma unroll 4
    for (int c = 0; c < KDIM; c++) {
        float4 w4 = *(const float4*)(proj_W + c * DMODEL + d4);
#pragma unroll
        for (int p = 0; p < 16; p++) {
            float s = cs[p * KDIM + c];
            acc[p].x = fmaf(s, w4.x, acc[p].x);
            acc[p].y = fmaf(s, w4.y, acc[p].y);
            acc[p].z = fmaf(s, w4.z, acc[p].z);
            acc[p].w = fmaf(s, w4.w, acc[p].w);
        }
    }
    float4 pb = *(const float4*)(proj_b + d4);
#pragma unroll
    for (int p = 0; p < 16; p++) {
        float4 o;
        o.x = acc[p].x + pb.x; o.y = acc[p].y + pb.y;
        o.z = acc[p].z + pb.z; o.w = acc[p].w + pb.w;
        *(float4*)(tokens + (long)(p0 + p) * DMODEL + d4) = o;
    }
}

// ---------------- launcher ----------------
extern "C" void kernel_launch(void* const* d_in, const int* in_sizes, int n_in,
                              void* d_out, int out_size)
{
    const float* x      = (const float*)d_in[0];
    const float* W1     = (const float*)d_in[1];
    const float* b1     = (const float*)d_in[2];
    const float* W2     = (const float*)d_in[3];
    const float* b2     = (const float*)d_in[4];
    const float* lift_W = (const float*)d_in[5];
    const float* lift_b = (const float*)d_in[6];
    const float* mu     = (const float*)d_in[7];
    const float* sigma  = (const float*)d_in[8];
    const float* proj_W = (const float*)d_in[9];
    const float* proj_b = (const float*)d_in[10];

    float* tokens = (float*)d_out;                        // [B,256,1024]
    float* ystar  = tokens + (long)BATCH * KSEL * DMODEL; // [B,4096]

    saliency_kernel<<<BATCH * (NPTS / (32 * TILES_PER_BLOCK)), 256>>>(x, W1, b1, W2, b2);
    scan_kernel<<<BATCH, 1024>>>(ystar);
    topk_kernel<<<BATCH, 1024>>>(ystar);
    lift_kernel<<<BATCH * KSEL / 8, 256>>>(x, lift_W, lift_b, mu, sigma);
    proj_kernel<<<BATCH * KSEL / 16, 256>>>(proj_W, proj_b, tokens);
}

// round 5
// speedup vs baseline: 1.0729x; 1.0729x over previous
#include <cuda_runtime.h>
#include <math.h>

#define BATCH 32
#define NPTS 4096
#define IDIM 125
#define ADIM 128
#define KDIM 64
#define DMODEL 1024
#define HID 64
#define KSEL 256
#define EPSV 1e-6f

// ---------------- scratch (device globals; no allocation allowed) ----------------
__device__ float g_sal[BATCH * NPTS];
__device__ float g_csal[BATCH * NPTS];
__device__ int   g_topidx[BATCH * KSEL];

// ---------------- kernel 1: fused saliency MLP (register-blocked) ----------------
// tile: 128 points x 64 hidden, 2 tiles per block (W1 stays resident).
// 256 threads; micro-tile 4 points x 8 hidden -> 32 FMA per 48B smem (1.5B/FMA).
// dynamic smem: W1s (8000 f) + sx (128*129 f) = 98048 B.
#define SAL_TILE_PTS 128
#define SAL_TILES 2
#define SX_STRIDE 129
__global__ __launch_bounds__(256) void saliency_kernel(
    const float* __restrict__ x, const float* __restrict__ W1,
    const float* __restrict__ b1, const float* __restrict__ W2,
    const float* __restrict__ b2)
{
    extern __shared__ float dynsm[];
    float* W1s = dynsm;                 // [125][64]
    float* sx  = dynsm + IDIM * HID;    // [128][129]

    const int ptsPerBlock = SAL_TILE_PTS * SAL_TILES;       // 256
    const int groupsPerBatch = NPTS / ptsPerBlock;          // 16
    const int b  = blockIdx.x / groupsPerBatch;
    const int gp = blockIdx.x % groupsPerBatch;
    const int tid = threadIdx.x;

    for (int i = tid; i < IDIM * HID; i += 256) W1s[i] = W1[i];

    const int hg = tid & 7;        // 8 hidden groups of 8
    const int pg = tid >> 3;       // 32 point groups of 4
    const int h0 = hg * 8;

    float4 b1a = *(const float4*)(b1 + h0);
    float4 b1b = *(const float4*)(b1 + h0 + 4);
    float4 w2a = *(const float4*)(W2 + h0);
    float4 w2b = *(const float4*)(W2 + h0 + 4);
    const float bias = b2[0];

    for (int t = 0; t < SAL_TILES; t++) {
        const int p0 = (gp * SAL_TILES + t) * SAL_TILE_PTS;
        const float* xbase = x + ((long)b * NPTS + p0) * IDIM;
        __syncthreads();
        for (int i = tid; i < SAL_TILE_PTS * IDIM; i += 256) {
            int p = i / IDIM, d = i - p * IDIM;
            sx[p * SX_STRIDE + d] = xbase[i];
        }
        __syncthreads();

        // accumulators: a[q][j], q=point-in-group, j=hidden-in-group
        float a0[8], a1[8], a2[8], a3[8];
        a0[0]=b1a.x; a0[1]=b1a.y; a0[2]=b1a.z; a0[3]=b1a.w; a0[4]=b1b.x; a0[5]=b1b.y; a0[6]=b1b.z; a0[7]=b1b.w;
#pragma unroll
        for (int j = 0; j < 8; j++) { a1[j]=a0[j]; a2[j]=a0[j]; a3[j]=a0[j]; }

        const float* r0 = sx + (pg * 4 + 0) * SX_STRIDE;
        const float* r1 = sx + (pg * 4 + 1) * SX_STRIDE;
        const float* r2 = sx + (pg * 4 + 2) * SX_STRIDE;
        const float* r3 = sx + (pg * 4 + 3) * SX_STRIDE;
#pragma unroll 5
        for (int d = 0; d < IDIM; d++) {
            float x0 = r0[d], x1 = r1[d], x2 = r2[d], x3 = r3[d];
            float4 wa = *(const float4*)(W1s + d * HID + h0);
            float4 wb = *(const float4*)(W1s + d * HID + h0 + 4);
            float w[8] = {wa.x, wa.y, wa.z, wa.w, wb.x, wb.y, wb.z, wb.w};
#pragma unroll
            for (int j = 0; j < 8; j++) {
                a0[j] = fmaf(x0, w[j], a0[j]);
                a1[j] = fmaf(x1, w[j], a1[j]);
                a2[j] = fmaf(x2, w[j], a2[j]);
                a3[j] = fmaf(x3, w[j], a3[j]);
            }
        }
        // relu + dot with W2 slice
        float w2[8] = {w2a.x, w2a.y, w2a.z, w2a.w, w2b.x, w2b.y, w2b.z, w2b.w};
        float s0 = 0.f, s1 = 0.f, s2 = 0.f, s3 = 0.f;
#pragma unroll
        for (int j = 0; j < 8; j++) {
            s0 = fmaf(fmaxf(a0[j], 0.f), w2[j], s0);
            s1 = fmaf(fmaxf(a1[j], 0.f), w2[j], s1);
            s2 = fmaf(fmaxf(a2[j], 0.f), w2[j], s2);
            s3 = fmaf(fmaxf(a3[j], 0.f), w2[j], s3);
        }
        // reduce across the 8 hg lanes (consecutive lanes, width 8)
#pragma unroll
        for (int off = 4; off > 0; off >>= 1) {
            s0 += __shfl_down_sync(0xFFFFFFFFu, s0, off, 8);
            s1 += __shfl_down_sync(0xFFFFFFFFu, s1, off, 8);
            s2 += __shfl_down_sync(0xFFFFFFFFu, s2, off, 8);
            s3 += __shfl_down_sync(0xFFFFFFFFu, s3, off, 8);
        }
        if (hg == 0) {
            float* o = g_sal + b * NPTS + p0 + pg * 4;
            float4 r;
            r.x = 1.f / (1.f + expf(-(s0 + bias)));
            r.y = 1.f / (1.f + expf(-(s1 + bias)));
            r.z = 1.f / (1.f + expf(-(s2 + bias)));
            r.w = 1.f / (1.f + expf(-(s3 + bias)));
            *(float4*)o = r;
        }
    }
}

// ---------------- kernel 2: per-batch softmax + cumsum ----------------
__global__ __launch_bounds__(1024) void scan_kernel(float* __restrict__ ystar)
{
    __shared__ float wsum[32];
    __shared__ float woff[32];
    __shared__ float wesum[32];
    __shared__ float total_sh;

    const int b = blockIdx.x;
    const int tid = threadIdx.x;
    const int lane = tid & 31, wid = tid >> 5;

    float4 s4 = *(const float4*)(g_sal + b * NPTS + tid * 4);
    float s0 = s4.x;
    float s1 = s0 + s4.y;
    float s2 = s1 + s4.z;
    float s3 = s2 + s4.w;

    float e0 = expf(2.f * s4.x), e1 = expf(2.f * s4.y);
    float e2 = expf(2.f * s4.z), e3 = expf(2.f * s4.w);
    float esum = e0 + e1 + e2 + e3;

    float t = s3, incl = t;
#pragma unroll
    for (int off = 1; off < 32; off <<= 1) {
        float v = __shfl_up_sync(0xFFFFFFFFu, incl, off);
        if (lane >= off) incl += v;
    }
    float er = esum;
#pragma unroll
    for (int off = 16; off > 0; off >>= 1) er += __shfl_down_sync(0xFFFFFFFFu, er, off);
    if (lane == 31) wsum[wid] = incl;
    if (lane == 0)  wesum[wid] = er;
    __syncthreads();
    if (wid == 0) {
        float v = wsum[lane];
        float inc = v;
#pragma unroll
        for (int off = 1; off < 32; off <<= 1) {
            float u = __shfl_up_sync(0xFFFFFFFFu, inc, off);
            if (lane >= off) inc += u;
        }
        woff[lane] = inc - v;
        float es = wesum[lane];
#pragma unroll
        for (int off = 16; off > 0; off >>= 1) es += __shfl_down_sync(0xFFFFFFFFu, es, off);
        if (lane == 0) total_sh = es;
    }
    __syncthreads();

    float base = woff[wid] + (incl - t);
    const float invn = 1.f / (float)NPTS;
    float4 c4;
    c4.x = (base + s0) * invn;
    c4.y = (base + s1) * invn;
    c4.z = (base + s2) * invn;
    c4.w = (base + s3) * invn;
    *(float4*)(g_csal + b * NPTS + tid * 4) = c4;

    float invtot = 1.f / total_sh;
    float4 y4;
    y4.x = e0 * invtot; y4.y = e1 * invtot; y4.z = e2 * invtot; y4.w = e3 * invtot;
    *(float4*)(ystar + b * NPTS + tid * 4) = y4;
}

// ---------------- kernel 3: per-batch top-256 via bitonic sort ----------------
__global__ __launch_bounds__(1024) void topk_kernel(const float* __restrict__ ystar)
{
    __shared__ unsigned long long keys[NPTS];
    const int b = blockIdx.x;
    const int tid = threadIdx.x;

    for (int i = tid; i < NPTS; i += 1024) {
        unsigned u = __float_as_uint(ystar[b * NPTS + i]);
        unsigned m = (u & 0x80000000u) ? ~u : (u | 0x80000000u);
        unsigned inv = ~m;
        keys[i] = ((unsigned long long)inv << 32) | (unsigned)i;
    }
    __syncthreads();

    for (int k = 2; k <= NPTS; k <<= 1) {
        for (int j = k >> 1; j > 0; j >>= 1) {
#pragma unroll 4
            for (int i = tid; i < NPTS; i += 1024) {
                int ixj = i ^ j;
                if (ixj > i) {
                    bool up = ((i & k) == 0);
                    unsigned long long a = keys[i];
                    unsigned long long c = keys[ixj];
                    if ((a > c) == up) { keys[i] = c; keys[ixj] = a; }
                }
            }
            __syncthreads();
        }
    }
    for (int t2 = tid; t2 < KSEL; t2 += 1024)
        g_topidx[b * KSEL + t2] = (int)(keys[t2] & 0xFFFFFFFFu);
}

// ---------------- kernel 4: fused anchor + normalize + lift + proj ----------------
// one block per 16 selected points; 256 threads.
// stage1 gather+normalize anchors -> a_s[16][132]
// stage2 cloud[16][64] = a_s @ lift_W + lift_b
// stage3 tokens = cloud @ proj_W + proj_b (proj_W streamed from L2)
#define AS_STRIDE 132
__global__ __launch_bounds__(256) void tail_kernel(
    const float* __restrict__ x, const float* __restrict__ lift_W,
    const float* __restrict__ lift_b, const float* __restrict__ mu,
    const float* __restrict__ sigma, const float* __restrict__ proj_W,
    const float* __restrict__ proj_b, float* __restrict__ tokens)
{
    __shared__ float Ws[ADIM * KDIM];      // 32KB
    __shared__ float a_s[16][AS_STRIDE];   // 8.25KB
    __shared__ float cs[16 * KDIM];        // 4KB

    const int tid = threadIdx.x;
    const int p0 = blockIdx.x * 16;        // selected-point base (0..8191)

    for (int i = tid; i < ADIM * KDIM; i += 256) Ws[i] = lift_W[i];

    // ---- stage 1: gather + L2-normalize + standardize ----
    {
        const int grp = tid >> 4;          // point 0..15
        const int sub = tid & 15;          // dim chunk: 8 dims each
        const int gk = p0 + grp;
        const int b = gk / KSEL;
        const int idx = g_topidx[gk];
        const float* xr = x + ((long)b * NPTS + idx) * IDIM;
        float sal = g_sal[b * NPTS + idx];
        float csv = g_csal[b * NPTS + idx];
        float pos = (float)idx * (1.f / (float)(NPTS - 1));

        float v[8];
#pragma unroll
        for (int q = 0; q < 8; q++) {
            int d = sub * 8 + q;
            float val;
            if (d < IDIM)       val = xr[d];
            else if (d == 125)  val = sal;
            else if (d == 126)  val = pos;
            else                val = csv;
            v[q] = val;
        }
        float ss = 0.f;
#pragma unroll
        for (int q = 0; q < 8; q++) ss = fmaf(v[q], v[q], ss);
#pragma unroll
        for (int off = 8; off > 0; off >>= 1)
            ss += __shfl_xor_sync(0xFFFFFFFFu, ss, off, 16);
        float inv_nrm = 1.f / (sqrtf(ss) + EPSV);
#pragma unroll
        for (int q = 0; q < 8; q++) {
            int d = sub * 8 + q;
            a_s[grp][d] = (v[q] * inv_nrm - mu[d]) / sigma[d];
        }
    }
    __syncthreads();

    // ---- stage 2: cloud = a_s @ lift_W + lift_b ----
    {
        const int pt = tid >> 4;
        const int c4 = (tid & 15) * 4;
        float4 acc = *(const float4*)(lift_b + c4);
#pragma unroll 8
        for (int d = 0; d < ADIM; d++) {
            float s = a_s[pt][d];
            float4 w = *(const float4*)(Ws + d * KDIM + c4);
            acc.x = fmaf(s, w.x, acc.x);
            acc.y = fmaf(s, w.y, acc.y);
            acc.z = fmaf(s, w.z, acc.z);
            acc.w = fmaf(s, w.w, acc.w);
        }
        *(float4*)(cs + pt * KDIM + c4) = acc;
    }
    __syncthreads();

    // ---- stage 3: tokens = cloud @ proj_W + proj_b ----
    {
        const int d4 = tid * 4;
        float4 acc[16];
#pragma unroll
        for (int p = 0; p < 16; p++) acc[p] = make_float4(0.f, 0.f, 0.f, 0.f);
#pragma unroll 4
        for (int c = 0; c < KDIM; c++) {
            float4 w4 = *(const float4*)(proj_W + c * DMODEL + d4);
#pragma unroll
            for (int p = 0; p < 16; p++) {
                float s = cs[p * KDIM + c];
                acc[p].x = fmaf(s, w4.x, acc[p].x);
                acc[p].y = fmaf(s, w4.y, acc[p].y);
                acc[p].z = fmaf(s, w4.z, acc[p].z);
                acc[p].w = fmaf(s, w4.w, acc[p].w);
            }
        }
        float4 pb = *(const float4*)(proj_b + d4);
#pragma unroll
        for (int p = 0; p < 16; p++) {
            float4 o;
            o.x = acc[p].x + pb.x; o.y = acc[p].y + pb.y;
            o.z = acc[p].z + pb.z; o.w = acc[p].w + pb.w;
            *(float4*)(tokens + (long)(p0 + p) * DMODEL + d4) = o;
        }
    }
}

// ---------------- launcher ----------------
extern "C" void kernel_launch(void* const* d_in, const int* in_sizes, int n_in,
                              void* d_out, int out_size)
{
    const float* x      = (const float*)d_in[0];
    const float* W1     = (const float*)d_in[1];
    const float* b1     = (const float*)d_in[2];
    const float* W2     = (const float*)d_in[3];
    const float* b2     = (const float*)d_in[4];
    const float* lift_W = (const float*)d_in[5];
    const float* lift_b = (const float*)d_in[6];
    const float* mu     = (const float*)d_in[7];
    const float* sigma  = (const float*)d_in[8];
    const float* proj_W = (const float*)d_in[9];
    const float* proj_b = (const float*)d_in[10];

    float* tokens = (float*)d_out;                        // [B,256,1024]
    float* ystar  = tokens + (long)BATCH * KSEL * DMODEL; // [B,4096]

    const int salSmem = (IDIM * HID + SAL_TILE_PTS * SX_STRIDE) * sizeof(float); // 98048 B
    cudaFuncSetAttribute(saliency_kernel, cudaFuncAttributeMaxDynamicSharedMemorySize, salSmem);

    saliency_kernel<<<BATCH * (NPTS / (SAL_TILE_PTS * SAL_TILES)), 256, salSmem>>>(x, W1, b1, W2, b2);
    scan_kernel<<<BATCH, 1024>>>(ystar);
    topk_kernel<<<BATCH, 1024>>>(ystar);
    tail_kernel<<<BATCH * KSEL / 16, 256>>>(x, lift_W, lift_b, mu, sigma,
                                            proj_W, proj_b, tokens);
}